// round 1
// baseline (speedup 1.0000x reference)
#include <cuda_runtime.h>
#include <math.h>
#include <stdint.h>

#define BB 4
#define SS 1024
#define DD 1024
#define HH 16
#define DHH 64
#define FFD 4096
#define LL 4
#define PP 1024     // 2*SPAN
#define SPAN_ 512
#define BS (BB*SS)  // 4096

// ---------------- scratch (static device globals; no allocation allowed) ----
__device__ float g_h  [BS*DD];
__device__ float g_q  [BS*DD];
__device__ float g_k  [BS*DD];
__device__ float g_v  [BS*DD];
__device__ float g_ctx[BS*DD];
__device__ float g_t2 [BS*DD];
__device__ float g_ff [(size_t)BS*FFD];
__device__ float g_posk[PP*DD];
__device__ float g_posq[PP*DD];
__device__ float g_s1 [(size_t)BB*HH*SS*SS];   // attention scores / probs (in-place)
__device__ float g_c2p[(size_t)BB*HH*SS*PP];
__device__ float g_p2c[(size_t)BB*HH*SS*PP];

// ---------------- embedding + LayerNorm + mask ------------------------------
__global__ __launch_bounds__(256) void embed_ln(
    const int* __restrict__ ids, const int* __restrict__ segs,
    const float* __restrict__ mask, const float* __restrict__ tok,
    const float* __restrict__ seg, const float* __restrict__ g,
    const float* __restrict__ b)
{
    int row = blockIdx.x;
    int tid = threadIdx.x;
    const float* t  = tok + (size_t)ids[row]  * DD;
    const float* sg = seg + (size_t)segs[row] * DD;

    float x[4];
    float s = 0.f;
    #pragma unroll
    for (int i = 0; i < 4; i++) {
        int c = tid + i * 256;
        x[i] = t[c] + sg[c];
        s += x[i];
    }
    __shared__ float red[256];
    red[tid] = s; __syncthreads();
    for (int o = 128; o > 0; o >>= 1) { if (tid < o) red[tid] += red[tid + o]; __syncthreads(); }
    float m = red[0] * (1.f / DD);
    __syncthreads();

    s = 0.f;
    #pragma unroll
    for (int i = 0; i < 4; i++) { float d = x[i] - m; s += d * d; }
    red[tid] = s; __syncthreads();
    for (int o = 128; o > 0; o >>= 1) { if (tid < o) red[tid] += red[tid + o]; __syncthreads(); }
    float inv = rsqrtf(red[0] * (1.f / DD) + 1e-12f);

    float mk = mask[row];
    #pragma unroll
    for (int i = 0; i < 4; i++) {
        int c = tid + i * 256;
        g_h[(size_t)row * DD + c] = ((x[i] - m) * inv * g[c] + b[c]) * mk;
    }
}

// ---------------- residual add + LayerNorm ----------------------------------
__global__ __launch_bounds__(256) void add_ln(
    const float* __restrict__ base, const float* __restrict__ addv,
    const float* __restrict__ g, const float* __restrict__ b,
    float* __restrict__ out)
{
    int row = blockIdx.x;
    int tid = threadIdx.x;
    size_t off = (size_t)row * DD;

    float x[4];
    float s = 0.f;
    #pragma unroll
    for (int i = 0; i < 4; i++) {
        int c = tid + i * 256;
        x[i] = base[off + c] + addv[off + c];
        s += x[i];
    }
    __shared__ float red[256];
    red[tid] = s; __syncthreads();
    for (int o = 128; o > 0; o >>= 1) { if (tid < o) red[tid] += red[tid + o]; __syncthreads(); }
    float m = red[0] * (1.f / DD);
    __syncthreads();

    s = 0.f;
    #pragma unroll
    for (int i = 0; i < 4; i++) { float d = x[i] - m; s += d * d; }
    red[tid] = s; __syncthreads();
    for (int o = 128; o > 0; o >>= 1) { if (tid < o) red[tid] += red[tid + o]; __syncthreads(); }
    float inv = rsqrtf(red[0] * (1.f / DD) + 1e-12f);

    #pragma unroll
    for (int i = 0; i < 4; i++) {
        int c = tid + i * 256;
        out[off + c] = (x[i] - m) * inv * g[c] + b[c];
    }
}

// ---------------- dense SGEMM: C = A[MxK] @ B[KxN] + bias, optional GELU ----
// All M, N multiples of 128, K multiple of 8. 256 threads, 8x8 per thread.
template <int ACT>
__global__ __launch_bounds__(256) void sgemm(
    const float* __restrict__ A, const float* __restrict__ B,
    const float* __restrict__ bias, float* __restrict__ C,
    int M, int N, int K)
{
    __shared__ float As[8][128];
    __shared__ float Bs[8][128];

    int tid = threadIdx.x;
    int bm = blockIdx.y * 128, bn = blockIdx.x * 128;

    int arow = tid >> 1, acol = (tid & 1) << 2;
    int brow = tid >> 5, bcol = (tid & 31) << 2;

    const float* Ap = A + (size_t)(bm + arow) * K + acol;
    const float* Bp = B + (size_t)brow * N + bn + bcol;

    float acc[8][8];
    #pragma unroll
    for (int i = 0; i < 8; i++)
        #pragma unroll
        for (int j = 0; j < 8; j++) acc[i][j] = 0.f;

    int tx = tid & 15, ty = tid >> 4;

    for (int k0 = 0; k0 < K; k0 += 8) {
        float4 a4 = *(const float4*)Ap; Ap += 8;
        float4 b4 = *(const float4*)Bp; Bp += (size_t)8 * N;

        As[acol + 0][arow] = a4.x;
        As[acol + 1][arow] = a4.y;
        As[acol + 2][arow] = a4.z;
        As[acol + 3][arow] = a4.w;
        *(float4*)&Bs[brow][bcol] = b4;
        __syncthreads();

        #pragma unroll
        for (int kk = 0; kk < 8; kk++) {
            float ar[8], br[8];
            #pragma unroll
            for (int i = 0; i < 8; i++) ar[i] = As[kk][ty * 8 + i];
            #pragma unroll
            for (int j = 0; j < 8; j++) br[j] = Bs[kk][tx * 8 + j];
            #pragma unroll
            for (int i = 0; i < 8; i++)
                #pragma unroll
                for (int j = 0; j < 8; j++) acc[i][j] += ar[i] * br[j];
        }
        __syncthreads();
    }

    #pragma unroll
    for (int i = 0; i < 8; i++) {
        int row = bm + ty * 8 + i;
        #pragma unroll
        for (int j = 0; j < 8; j++) {
            int col = bn + tx * 8 + j;
            float val = acc[i][j] + bias[col];
            if (ACT == 1) val = 0.5f * val * (1.f + erff(val * 0.70710678118654752f));
            C[(size_t)row * N + col] = val;
        }
    }
}

// ---------------- batched NT GEMM for attention scores (K = 64) -------------
// C[bh, m, n] = sum_d A[b,m,h,d] * B[b,n,h,d]; output tile 64x64, K=64 one pass.
// A/B rows have leading dim DD; per-b stride passed (0 for shared pos tables).
__global__ __launch_bounds__(256) void score_gemm(
    const float* __restrict__ A, long long aStrideB,
    const float* __restrict__ B, long long bStrideB,
    float* __restrict__ C)
{
    int bh = blockIdx.z;
    int b = bh / HH, h = bh % HH;

    const float* Ag = A + (size_t)b * aStrideB + h * DHH + (size_t)(blockIdx.y * 64) * DD;
    const float* Bg = B + (size_t)b * bStrideB + h * DHH + (size_t)(blockIdx.x * 64) * DD;

    __shared__ float As[64][65];
    __shared__ float Bs[64][65];

    int tid = threadIdx.x;
    for (int i = tid; i < 1024; i += 256) {
        int r = i >> 4, c = (i & 15) << 2;
        float4 va = *(const float4*)(Ag + (size_t)r * DD + c);
        As[r][c] = va.x; As[r][c + 1] = va.y; As[r][c + 2] = va.z; As[r][c + 3] = va.w;
        float4 vb = *(const float4*)(Bg + (size_t)r * DD + c);
        Bs[r][c] = vb.x; Bs[r][c + 1] = vb.y; Bs[r][c + 2] = vb.z; Bs[r][c + 3] = vb.w;
    }
    __syncthreads();

    int tx = tid & 15, ty = tid >> 4;
    float acc[4][4];
    #pragma unroll
    for (int i = 0; i < 4; i++)
        #pragma unroll
        for (int j = 0; j < 4; j++) acc[i][j] = 0.f;

    #pragma unroll 16
    for (int k = 0; k < 64; k++) {
        float ar[4], br[4];
        #pragma unroll
        for (int i = 0; i < 4; i++) ar[i] = As[ty * 4 + i][k];
        #pragma unroll
        for (int j = 0; j < 4; j++) br[j] = Bs[tx * 4 + j][k];
        #pragma unroll
        for (int i = 0; i < 4; i++)
            #pragma unroll
            for (int j = 0; j < 4; j++) acc[i][j] += ar[i] * br[j];
    }

    float* Cg = C + (size_t)bh * SS * 1024;
    #pragma unroll
    for (int i = 0; i < 4; i++) {
        int row = blockIdx.y * 64 + ty * 4 + i;
        #pragma unroll
        for (int j = 0; j < 4; j++) {
            int col = blockIdx.x * 64 + tx * 4 + j;
            Cg[(size_t)row * 1024 + col] = acc[i][j];
        }
    }
}

// ---------------- fused relative-bias gather + mask + softmax ---------------
// att (in/out) = softmax_k( scale*(s1 + c2p[q,idx] + p2c[k,idx]) + (1-mask)*NEG )
__global__ __launch_bounds__(256) void softmax_rel(
    const float* __restrict__ c2p, const float* __restrict__ p2c,
    const float* __restrict__ mask, float* __restrict__ att)
{
    int bh = blockIdx.y, q = blockIdx.x;
    int b = bh / HH;
    int tid = threadIdx.x;
    size_t rowOff = ((size_t)bh * SS + q) * SS;
    const float scale = 0.07216878364870323f; // 1/sqrt(64*3)

    float v[4];
    #pragma unroll
    for (int t = 0; t < 4; t++) {
        int k = tid + t * 256;
        int idx = q - k + SPAN_;
        idx = min(max(idx, 0), PP - 1);
        float s = att[rowOff + k]
                + c2p[((size_t)bh * SS + q) * PP + idx]
                + p2c[((size_t)bh * SS + k) * PP + idx];
        v[t] = s * scale + (1.f - mask[b * SS + k]) * -1e9f;
    }

    __shared__ float red[256];
    float m = fmaxf(fmaxf(v[0], v[1]), fmaxf(v[2], v[3]));
    red[tid] = m; __syncthreads();
    for (int o = 128; o > 0; o >>= 1) { if (tid < o) red[tid] = fmaxf(red[tid], red[tid + o]); __syncthreads(); }
    m = red[0];
    __syncthreads();

    float s = 0.f;
    #pragma unroll
    for (int t = 0; t < 4; t++) { v[t] = expf(v[t] - m); s += v[t]; }
    red[tid] = s; __syncthreads();
    for (int o = 128; o > 0; o >>= 1) { if (tid < o) red[tid] += red[tid + o]; __syncthreads(); }
    float inv = 1.f / red[0];

    #pragma unroll
    for (int t = 0; t < 4; t++) att[rowOff + tid + t * 256] = v[t] * inv;
}

// ---------------- ctx = probs @ V (batched, N = 64) --------------------------
__global__ __launch_bounds__(256) void ctx_gemm(
    const float* __restrict__ P, const float* __restrict__ V,
    float* __restrict__ O)
{
    int bh = blockIdx.z;
    int b = bh / HH, h = bh % HH;

    const float* Pg = P + (size_t)bh * SS * SS + (size_t)(blockIdx.x * 64) * SS;
    const float* Vg = V + (size_t)b * SS * DD + h * DHH;

    __shared__ float As[64][17];
    __shared__ float Bs[16][64];

    int tid = threadIdx.x;
    int tx = tid & 15, ty = tid >> 4;

    float acc[4][4];
    #pragma unroll
    for (int i = 0; i < 4; i++)
        #pragma unroll
        for (int j = 0; j < 4; j++) acc[i][j] = 0.f;

    int ra = tid >> 2, ca = (tid & 3) << 2;
    int rb = tid >> 4, cb = (tid & 15) << 2;

    for (int k0 = 0; k0 < SS; k0 += 16) {
        float4 va = *(const float4*)(Pg + (size_t)ra * SS + k0 + ca);
        As[ra][ca] = va.x; As[ra][ca + 1] = va.y; As[ra][ca + 2] = va.z; As[ra][ca + 3] = va.w;
        float4 vb = *(const float4*)(Vg + (size_t)(k0 + rb) * DD + cb);
        Bs[rb][cb] = vb.x; Bs[rb][cb + 1] = vb.y; Bs[rb][cb + 2] = vb.z; Bs[rb][cb + 3] = vb.w;
        __syncthreads();

        #pragma unroll
        for (int kk = 0; kk < 16; kk++) {
            float ar[4], br[4];
            #pragma unroll
            for (int i = 0; i < 4; i++) ar[i] = As[ty * 4 + i][kk];
            #pragma unroll
            for (int j = 0; j < 4; j++) br[j] = Bs[kk][tx * 4 + j];
            #pragma unroll
            for (int i = 0; i < 4; i++)
                #pragma unroll
                for (int j = 0; j < 4; j++) acc[i][j] += ar[i] * br[j];
        }
        __syncthreads();
    }

    #pragma unroll
    for (int i = 0; i < 4; i++) {
        int row = blockIdx.x * 64 + ty * 4 + i;
        #pragma unroll
        for (int j = 0; j < 4; j++) {
            O[((size_t)b * SS + row) * DD + h * DHH + tx * 4 + j] = acc[i][j];
        }
    }
}

// ---------------- host orchestration ----------------------------------------
extern "C" void kernel_launch(void* const* d_in, const int* in_sizes, int n_in,
                              void* d_out, int out_size)
{
    const int*   ids  = (const int*)d_in[0];
    const int*   segs = (const int*)d_in[1];
    const float* mask = (const float*)d_in[2];
    const float* tok  = (const float*)d_in[3];
    const float* seg  = (const float*)d_in[4];
    const float* elg  = (const float*)d_in[5];
    const float* elb  = (const float*)d_in[6];
    const float* rel  = (const float*)d_in[7];
    const float* Wq = (const float*)d_in[8],  *bq = (const float*)d_in[9];
    const float* Wk = (const float*)d_in[10], *bk = (const float*)d_in[11];
    const float* Wv = (const float*)d_in[12], *bv = (const float*)d_in[13];
    const float* Wo = (const float*)d_in[14], *bo = (const float*)d_in[15];
    const float* l1g = (const float*)d_in[16], *l1b = (const float*)d_in[17];
    const float* W1 = (const float*)d_in[18], *b1 = (const float*)d_in[19];
    const float* W2 = (const float*)d_in[20], *b2 = (const float*)d_in[21];
    const float* l2g = (const float*)d_in[22], *l2b = (const float*)d_in[23];

    float *h, *q, *k, *v, *ctx, *t2, *ff, *posk, *posq, *s1, *c2p, *p2c;
    cudaGetSymbolAddress((void**)&h,    g_h);
    cudaGetSymbolAddress((void**)&q,    g_q);
    cudaGetSymbolAddress((void**)&k,    g_k);
    cudaGetSymbolAddress((void**)&v,    g_v);
    cudaGetSymbolAddress((void**)&ctx,  g_ctx);
    cudaGetSymbolAddress((void**)&t2,   g_t2);
    cudaGetSymbolAddress((void**)&ff,   g_ff);
    cudaGetSymbolAddress((void**)&posk, g_posk);
    cudaGetSymbolAddress((void**)&posq, g_posq);
    cudaGetSymbolAddress((void**)&s1,   g_s1);
    cudaGetSymbolAddress((void**)&c2p,  g_c2p);
    cudaGetSymbolAddress((void**)&p2c,  g_p2c);

    embed_ln<<<BS, 256>>>(ids, segs, mask, tok, seg, elg, elb);

    dim3 gQKV(DD / 128, BS / 128);       // (8, 32)
    dim3 gPos(DD / 128, PP / 128);       // (8, 8)
    dim3 gScore(16, 16, BB * HH);        // 64x64 tiles over 1024x1024, 64 batches
    dim3 gSoft(SS, BB * HH);
    dim3 gCtx(16, 1, BB * HH);
    dim3 gF1(FFD / 128, BS / 128);       // (32, 32)
    dim3 gF2(DD / 128, BS / 128);

    for (int l = 0; l < LL; l++) {
        const float* wq = Wq + (size_t)l * DD * DD; const float* bq_ = bq + (size_t)l * DD;
        const float* wk = Wk + (size_t)l * DD * DD; const float* bk_ = bk + (size_t)l * DD;
        const float* wv = Wv + (size_t)l * DD * DD; const float* bv_ = bv + (size_t)l * DD;
        const float* wo = Wo + (size_t)l * DD * DD; const float* bo_ = bo + (size_t)l * DD;
        const float* w1 = W1 + (size_t)l * DD * FFD; const float* b1_ = b1 + (size_t)l * FFD;
        const float* w2 = W2 + (size_t)l * FFD * DD; const float* b2_ = b2 + (size_t)l * DD;
        const float* g1 = l1g + (size_t)l * DD; const float* be1 = l1b + (size_t)l * DD;
        const float* g2 = l2g + (size_t)l * DD; const float* be2 = l2b + (size_t)l * DD;

        sgemm<0><<<gQKV, 256>>>(h, wq, bq_, q, BS, DD, DD);
        sgemm<0><<<gQKV, 256>>>(h, wk, bk_, k, BS, DD, DD);
        sgemm<0><<<gQKV, 256>>>(h, wv, bv_, v, BS, DD, DD);
        sgemm<0><<<gPos, 256>>>(rel, wk, bk_, posk, PP, DD, DD);
        sgemm<0><<<gPos, 256>>>(rel, wq, bq_, posq, PP, DD, DD);

        score_gemm<<<gScore, 256>>>(q, (long long)SS * DD, k,    (long long)SS * DD, s1);
        score_gemm<<<gScore, 256>>>(q, (long long)SS * DD, posk, 0LL,                c2p);
        score_gemm<<<gScore, 256>>>(k, (long long)SS * DD, posq, 0LL,                p2c);

        softmax_rel<<<gSoft, 256>>>(c2p, p2c, mask, s1);

        ctx_gemm<<<gCtx, 256>>>(s1, v, ctx);

        sgemm<0><<<gQKV, 256>>>(ctx, wo, bo_, t2, BS, DD, DD);
        add_ln<<<BS, 256>>>(h, t2, g1, be1, h);

        sgemm<1><<<gF1, 256>>>(h, w1, b1_, ff, BS, FFD, DD);
        sgemm<0><<<gF2, 256>>>(ff, w2, b2_, t2, BS, DD, FFD);
        add_ln<<<BS, 256>>>(h, t2, g2, be2, h);
    }

    cudaMemcpyAsync(d_out, h, (size_t)BS * DD * sizeof(float),
                    cudaMemcpyDeviceToDevice);
}

// round 2
// speedup vs baseline: 1.0015x; 1.0015x over previous
#include <cuda_runtime.h>
#include <math.h>
#include <stdint.h>

#define BB 4
#define SS 1024
#define DD 1024
#define HH 16
#define DHH 64
#define FFD 4096
#define LL 4
#define PP 1024     // 2*SPAN
#define SPAN_ 512
#define BS (BB*SS)  // 4096

// ---------------- scratch (static device globals; no allocation allowed) ----
__device__ float g_h  [BS*DD];
__device__ float g_q  [BS*DD];
__device__ float g_k  [BS*DD];
__device__ float g_v  [BS*DD];
__device__ float g_ctx[BS*DD];
__device__ float g_t2 [BS*DD];
__device__ float g_ff [(size_t)BS*FFD];
__device__ float g_posk[PP*DD];
__device__ float g_posq[PP*DD];
__device__ float g_s1 [(size_t)BB*HH*SS*SS];   // attention scores / probs (in-place)
__device__ float g_c2p[(size_t)BB*HH*SS*PP];
__device__ float g_p2c[(size_t)BB*HH*SS*PP];

// ---------------- embedding + LayerNorm + mask ------------------------------
__global__ __launch_bounds__(256) void embed_ln(
    const int* __restrict__ ids, const int* __restrict__ segs,
    const float* __restrict__ mask, const float* __restrict__ tok,
    const float* __restrict__ seg, const float* __restrict__ g,
    const float* __restrict__ b)
{
    int row = blockIdx.x;
    int tid = threadIdx.x;
    const float* t  = tok + (size_t)ids[row]  * DD;
    const float* sg = seg + (size_t)segs[row] * DD;

    float x[4];
    float s = 0.f;
    #pragma unroll
    for (int i = 0; i < 4; i++) {
        int c = tid + i * 256;
        x[i] = t[c] + sg[c];
        s += x[i];
    }
    __shared__ float red[256];
    red[tid] = s; __syncthreads();
    for (int o = 128; o > 0; o >>= 1) { if (tid < o) red[tid] += red[tid + o]; __syncthreads(); }
    float m = red[0] * (1.f / DD);
    __syncthreads();

    s = 0.f;
    #pragma unroll
    for (int i = 0; i < 4; i++) { float d = x[i] - m; s += d * d; }
    red[tid] = s; __syncthreads();
    for (int o = 128; o > 0; o >>= 1) { if (tid < o) red[tid] += red[tid + o]; __syncthreads(); }
    float inv = rsqrtf(red[0] * (1.f / DD) + 1e-12f);

    float mk = mask[row];
    #pragma unroll
    for (int i = 0; i < 4; i++) {
        int c = tid + i * 256;
        g_h[(size_t)row * DD + c] = ((x[i] - m) * inv * g[c] + b[c]) * mk;
    }
}

// ---------------- residual add + LayerNorm ----------------------------------
__global__ __launch_bounds__(256) void add_ln(
    const float* __restrict__ base, const float* __restrict__ addv,
    const float* __restrict__ g, const float* __restrict__ b,
    float* __restrict__ out)
{
    int row = blockIdx.x;
    int tid = threadIdx.x;
    size_t off = (size_t)row * DD;

    float x[4];
    float s = 0.f;
    #pragma unroll
    for (int i = 0; i < 4; i++) {
        int c = tid + i * 256;
        x[i] = base[off + c] + addv[off + c];
        s += x[i];
    }
    __shared__ float red[256];
    red[tid] = s; __syncthreads();
    for (int o = 128; o > 0; o >>= 1) { if (tid < o) red[tid] += red[tid + o]; __syncthreads(); }
    float m = red[0] * (1.f / DD);
    __syncthreads();

    s = 0.f;
    #pragma unroll
    for (int i = 0; i < 4; i++) { float d = x[i] - m; s += d * d; }
    red[tid] = s; __syncthreads();
    for (int o = 128; o > 0; o >>= 1) { if (tid < o) red[tid] += red[tid + o]; __syncthreads(); }
    float inv = rsqrtf(red[0] * (1.f / DD) + 1e-12f);

    #pragma unroll
    for (int i = 0; i < 4; i++) {
        int c = tid + i * 256;
        out[off + c] = (x[i] - m) * inv * g[c] + b[c];
    }
}

// ---------------- dense SGEMM: C = A[MxK] @ B[KxN] + bias, optional GELU ----
// All M, N multiples of 128, K multiple of 8. 256 threads, 8x8 per thread.
template <int ACT>
__global__ __launch_bounds__(256) void sgemm(
    const float* __restrict__ A, const float* __restrict__ B,
    const float* __restrict__ bias, float* __restrict__ C,
    int M, int N, int K)
{
    __shared__ float As[8][128];
    __shared__ float Bs[8][128];

    int tid = threadIdx.x;
    int bm = blockIdx.y * 128, bn = blockIdx.x * 128;

    int arow = tid >> 1, acol = (tid & 1) << 2;
    int brow = tid >> 5, bcol = (tid & 31) << 2;

    const float* Ap = A + (size_t)(bm + arow) * K + acol;
    const float* Bp = B + (size_t)brow * N + bn + bcol;

    float acc[8][8];
    #pragma unroll
    for (int i = 0; i < 8; i++)
        #pragma unroll
        for (int j = 0; j < 8; j++) acc[i][j] = 0.f;

    int tx = tid & 15, ty = tid >> 4;

    for (int k0 = 0; k0 < K; k0 += 8) {
        float4 a4 = *(const float4*)Ap; Ap += 8;
        float4 b4 = *(const float4*)Bp; Bp += (size_t)8 * N;

        As[acol + 0][arow] = a4.x;
        As[acol + 1][arow] = a4.y;
        As[acol + 2][arow] = a4.z;
        As[acol + 3][arow] = a4.w;
        *(float4*)&Bs[brow][bcol] = b4;
        __syncthreads();

        #pragma unroll
        for (int kk = 0; kk < 8; kk++) {
            float ar[8], br[8];
            #pragma unroll
            for (int i = 0; i < 8; i++) ar[i] = As[kk][ty * 8 + i];
            #pragma unroll
            for (int j = 0; j < 8; j++) br[j] = Bs[kk][tx * 8 + j];
            #pragma unroll
            for (int i = 0; i < 8; i++)
                #pragma unroll
                for (int j = 0; j < 8; j++) acc[i][j] += ar[i] * br[j];
        }
        __syncthreads();
    }

    #pragma unroll
    for (int i = 0; i < 8; i++) {
        int row = bm + ty * 8 + i;
        #pragma unroll
        for (int j = 0; j < 8; j++) {
            int col = bn + tx * 8 + j;
            float val = acc[i][j] + bias[col];
            if (ACT == 1) val = 0.5f * val * (1.f + erff(val * 0.70710678118654752f));
            C[(size_t)row * N + col] = val;
        }
    }
}

// ---------------- batched NT GEMM for attention scores (K = 64) -------------
// C[bh, m, n] = sum_d A[b,m,h,d] * B[b,n,h,d]; output tile 64x64, K=64 one pass.
// A/B rows have leading dim DD; per-b stride passed (0 for shared pos tables).
__global__ __launch_bounds__(256) void score_gemm(
    const float* __restrict__ A, long long aStrideB,
    const float* __restrict__ B, long long bStrideB,
    float* __restrict__ C)
{
    int bh = blockIdx.z;
    int b = bh / HH, h = bh % HH;

    const float* Ag = A + (size_t)b * aStrideB + h * DHH + (size_t)(blockIdx.y * 64) * DD;
    const float* Bg = B + (size_t)b * bStrideB + h * DHH + (size_t)(blockIdx.x * 64) * DD;

    __shared__ float As[64][65];
    __shared__ float Bs[64][65];

    int tid = threadIdx.x;
    for (int i = tid; i < 1024; i += 256) {
        int r = i >> 4, c = (i & 15) << 2;
        float4 va = *(const float4*)(Ag + (size_t)r * DD + c);
        As[r][c] = va.x; As[r][c + 1] = va.y; As[r][c + 2] = va.z; As[r][c + 3] = va.w;
        float4 vb = *(const float4*)(Bg + (size_t)r * DD + c);
        Bs[r][c] = vb.x; Bs[r][c + 1] = vb.y; Bs[r][c + 2] = vb.z; Bs[r][c + 3] = vb.w;
    }
    __syncthreads();

    int tx = tid & 15, ty = tid >> 4;
    float acc[4][4];
    #pragma unroll
    for (int i = 0; i < 4; i++)
        #pragma unroll
        for (int j = 0; j < 4; j++) acc[i][j] = 0.f;

    #pragma unroll 16
    for (int k = 0; k < 64; k++) {
        float ar[4], br[4];
        #pragma unroll
        for (int i = 0; i < 4; i++) ar[i] = As[ty * 4 + i][k];
        #pragma unroll
        for (int j = 0; j < 4; j++) br[j] = Bs[tx * 4 + j][k];
        #pragma unroll
        for (int i = 0; i < 4; i++)
            #pragma unroll
            for (int j = 0; j < 4; j++) acc[i][j] += ar[i] * br[j];
    }

    float* Cg = C + (size_t)bh * SS * 1024;
    #pragma unroll
    for (int i = 0; i < 4; i++) {
        int row = blockIdx.y * 64 + ty * 4 + i;
        #pragma unroll
        for (int j = 0; j < 4; j++) {
            int col = blockIdx.x * 64 + tx * 4 + j;
            Cg[(size_t)row * 1024 + col] = acc[i][j];
        }
    }
}

// ---------------- fused relative-bias gather + mask + softmax ---------------
// att (in/out) = softmax_k( scale*(s1 + c2p[q,idx] + p2c[k,idx]) + (1-mask)*NEG )
__global__ __launch_bounds__(256) void softmax_rel(
    const float* __restrict__ c2p, const float* __restrict__ p2c,
    const float* __restrict__ mask, float* __restrict__ att)
{
    int bh = blockIdx.y, q = blockIdx.x;
    int b = bh / HH;
    int tid = threadIdx.x;
    size_t rowOff = ((size_t)bh * SS + q) * SS;
    const float scale = 0.07216878364870323f; // 1/sqrt(64*3)

    float v[4];
    #pragma unroll
    for (int t = 0; t < 4; t++) {
        int k = tid + t * 256;
        int idx = q - k + SPAN_;
        idx = min(max(idx, 0), PP - 1);
        float s = att[rowOff + k]
                + c2p[((size_t)bh * SS + q) * PP + idx]
                + p2c[((size_t)bh * SS + k) * PP + idx];
        v[t] = s * scale + (1.f - mask[b * SS + k]) * -1e9f;
    }

    __shared__ float red[256];
    float m = fmaxf(fmaxf(v[0], v[1]), fmaxf(v[2], v[3]));
    red[tid] = m; __syncthreads();
    for (int o = 128; o > 0; o >>= 1) { if (tid < o) red[tid] = fmaxf(red[tid], red[tid + o]); __syncthreads(); }
    m = red[0];
    __syncthreads();

    float s = 0.f;
    #pragma unroll
    for (int t = 0; t < 4; t++) { v[t] = expf(v[t] - m); s += v[t]; }
    red[tid] = s; __syncthreads();
    for (int o = 128; o > 0; o >>= 1) { if (tid < o) red[tid] += red[tid + o]; __syncthreads(); }
    float inv = 1.f / red[0];

    #pragma unroll
    for (int t = 0; t < 4; t++) att[rowOff + tid + t * 256] = v[t] * inv;
}

// ---------------- ctx = probs @ V (batched, N = 64) --------------------------
__global__ __launch_bounds__(256) void ctx_gemm(
    const float* __restrict__ P, const float* __restrict__ V,
    float* __restrict__ O)
{
    int bh = blockIdx.z;
    int b = bh / HH, h = bh % HH;

    const float* Pg = P + (size_t)bh * SS * SS + (size_t)(blockIdx.x * 64) * SS;
    const float* Vg = V + (size_t)b * SS * DD + h * DHH;

    __shared__ float As[64][17];
    __shared__ float Bs[16][64];

    int tid = threadIdx.x;
    int tx = tid & 15, ty = tid >> 4;

    float acc[4][4];
    #pragma unroll
    for (int i = 0; i < 4; i++)
        #pragma unroll
        for (int j = 0; j < 4; j++) acc[i][j] = 0.f;

    int ra = tid >> 2, ca = (tid & 3) << 2;
    int rb = tid >> 4, cb = (tid & 15) << 2;

    for (int k0 = 0; k0 < SS; k0 += 16) {
        float4 va = *(const float4*)(Pg + (size_t)ra * SS + k0 + ca);
        As[ra][ca] = va.x; As[ra][ca + 1] = va.y; As[ra][ca + 2] = va.z; As[ra][ca + 3] = va.w;
        float4 vb = *(const float4*)(Vg + (size_t)(k0 + rb) * DD + cb);
        Bs[rb][cb] = vb.x; Bs[rb][cb + 1] = vb.y; Bs[rb][cb + 2] = vb.z; Bs[rb][cb + 3] = vb.w;
        __syncthreads();

        #pragma unroll
        for (int kk = 0; kk < 16; kk++) {
            float ar[4], br[4];
            #pragma unroll
            for (int i = 0; i < 4; i++) ar[i] = As[ty * 4 + i][kk];
            #pragma unroll
            for (int j = 0; j < 4; j++) br[j] = Bs[kk][tx * 4 + j];
            #pragma unroll
            for (int i = 0; i < 4; i++)
                #pragma unroll
                for (int j = 0; j < 4; j++) acc[i][j] += ar[i] * br[j];
        }
        __syncthreads();
    }

    #pragma unroll
    for (int i = 0; i < 4; i++) {
        int row = blockIdx.x * 64 + ty * 4 + i;
        #pragma unroll
        for (int j = 0; j < 4; j++) {
            O[((size_t)b * SS + row) * DD + h * DHH + tx * 4 + j] = acc[i][j];
        }
    }
}

// ---------------- host orchestration ----------------------------------------
extern "C" void kernel_launch(void* const* d_in, const int* in_sizes, int n_in,
                              void* d_out, int out_size)
{
    const int*   ids  = (const int*)d_in[0];
    const int*   segs = (const int*)d_in[1];
    const float* mask = (const float*)d_in[2];
    const float* tok  = (const float*)d_in[3];
    const float* seg  = (const float*)d_in[4];
    const float* elg  = (const float*)d_in[5];
    const float* elb  = (const float*)d_in[6];
    const float* rel  = (const float*)d_in[7];
    const float* Wq = (const float*)d_in[8],  *bq = (const float*)d_in[9];
    const float* Wk = (const float*)d_in[10], *bk = (const float*)d_in[11];
    const float* Wv = (const float*)d_in[12], *bv = (const float*)d_in[13];
    const float* Wo = (const float*)d_in[14], *bo = (const float*)d_in[15];
    const float* l1g = (const float*)d_in[16], *l1b = (const float*)d_in[17];
    const float* W1 = (const float*)d_in[18], *b1 = (const float*)d_in[19];
    const float* W2 = (const float*)d_in[20], *b2 = (const float*)d_in[21];
    const float* l2g = (const float*)d_in[22], *l2b = (const float*)d_in[23];

    float *h, *q, *k, *v, *ctx, *t2, *ff, *posk, *posq, *s1, *c2p, *p2c;
    cudaGetSymbolAddress((void**)&h,    g_h);
    cudaGetSymbolAddress((void**)&q,    g_q);
    cudaGetSymbolAddress((void**)&k,    g_k);
    cudaGetSymbolAddress((void**)&v,    g_v);
    cudaGetSymbolAddress((void**)&ctx,  g_ctx);
    cudaGetSymbolAddress((void**)&t2,   g_t2);
    cudaGetSymbolAddress((void**)&ff,   g_ff);
    cudaGetSymbolAddress((void**)&posk, g_posk);
    cudaGetSymbolAddress((void**)&posq, g_posq);
    cudaGetSymbolAddress((void**)&s1,   g_s1);
    cudaGetSymbolAddress((void**)&c2p,  g_c2p);
    cudaGetSymbolAddress((void**)&p2c,  g_p2c);

    embed_ln<<<BS, 256>>>(ids, segs, mask, tok, seg, elg, elb);

    dim3 gQKV(DD / 128, BS / 128);       // (8, 32)
    dim3 gPos(DD / 128, PP / 128);       // (8, 8)
    dim3 gScore(16, 16, BB * HH);        // 64x64 tiles over 1024x1024, 64 batches
    dim3 gSoft(SS, BB * HH);
    dim3 gCtx(16, 1, BB * HH);
    dim3 gF1(FFD / 128, BS / 128);       // (32, 32)
    dim3 gF2(DD / 128, BS / 128);

    for (int l = 0; l < LL; l++) {
        const float* wq = Wq + (size_t)l * DD * DD; const float* bq_ = bq + (size_t)l * DD;
        const float* wk = Wk + (size_t)l * DD * DD; const float* bk_ = bk + (size_t)l * DD;
        const float* wv = Wv + (size_t)l * DD * DD; const float* bv_ = bv + (size_t)l * DD;
        const float* wo = Wo + (size_t)l * DD * DD; const float* bo_ = bo + (size_t)l * DD;
        const float* w1 = W1 + (size_t)l * DD * FFD; const float* b1_ = b1 + (size_t)l * FFD;
        const float* w2 = W2 + (size_t)l * FFD * DD; const float* b2_ = b2 + (size_t)l * DD;
        const float* g1 = l1g + (size_t)l * DD; const float* be1 = l1b + (size_t)l * DD;
        const float* g2 = l2g + (size_t)l * DD; const float* be2 = l2b + (size_t)l * DD;

        sgemm<0><<<gQKV, 256>>>(h, wq, bq_, q, BS, DD, DD);
        sgemm<0><<<gQKV, 256>>>(h, wk, bk_, k, BS, DD, DD);
        sgemm<0><<<gQKV, 256>>>(h, wv, bv_, v, BS, DD, DD);
        sgemm<0><<<gPos, 256>>>(rel, wk, bk_, posk, PP, DD, DD);
        sgemm<0><<<gPos, 256>>>(rel, wq, bq_, posq, PP, DD, DD);

        score_gemm<<<gScore, 256>>>(q, (long long)SS * DD, k,    (long long)SS * DD, s1);
        score_gemm<<<gScore, 256>>>(q, (long long)SS * DD, posk, 0LL,                c2p);
        score_gemm<<<gScore, 256>>>(k, (long long)SS * DD, posq, 0LL,                p2c);

        softmax_rel<<<gSoft, 256>>>(c2p, p2c, mask, s1);

        ctx_gemm<<<gCtx, 256>>>(s1, v, ctx);

        sgemm<0><<<gQKV, 256>>>(ctx, wo, bo_, t2, BS, DD, DD);
        add_ln<<<BS, 256>>>(h, t2, g1, be1, h);

        sgemm<1><<<gF1, 256>>>(h, w1, b1_, ff, BS, FFD, DD);
        sgemm<0><<<gF2, 256>>>(ff, w2, b2_, t2, BS, DD, FFD);
        add_ln<<<BS, 256>>>(h, t2, g2, be2, h);
    }

    cudaMemcpyAsync(d_out, h, (size_t)BS * DD * sizeof(float),
                    cudaMemcpyDeviceToDevice);
}

// round 5
// speedup vs baseline: 2.8355x; 2.8314x over previous
#include <cuda_runtime.h>
#include <cuda_fp16.h>
#include <math.h>
#include <stdint.h>

#define BB 4
#define SS 1024
#define DD 1024
#define HH 16
#define DHH 64
#define FFD 4096
#define LL 4
#define PP 1024
#define SPAN_ 512
#define BS (BB*SS)

typedef long long ll;
typedef __half hf;

// ---------------- scratch ------------------------------------------------------
__device__ float g_h [BS*DD];
__device__ float g_t2[BS*DD];

__device__ hf hb_hi[BS*DD], hb_lo[BS*DD];
__device__ hf qb   [BS*DD];
__device__ hf kb   [BS*DD];
__device__ hf vb   [BS*DD];
__device__ hf cx_hi[BS*DD], cx_lo[BS*DD];
__device__ hf ff_hi[(size_t)BS*FFD], ff_lo[(size_t)BS*FFD];
__device__ hf rl_hi[PP*DD], rl_lo[PP*DD];
__device__ hf pkb  [PP*DD];
__device__ hf pqb  [PP*DD];
__device__ hf wqt_hi[DD*DD], wqt_lo[DD*DD];
__device__ hf wkt_hi[DD*DD], wkt_lo[DD*DD];
__device__ hf wvt_hi[DD*DD], wvt_lo[DD*DD];
__device__ hf wot_hi[DD*DD], wot_lo[DD*DD];
__device__ hf w1t_hi[(size_t)FFD*DD], w1t_lo[(size_t)FFD*DD];
__device__ hf w2t_hi[(size_t)DD*FFD], w2t_lo[(size_t)DD*FFD];
__device__ hf vtb  [(size_t)BB*HH*DHH*SS];
__device__ hf prb  [(size_t)BB*HH*SS*SS];
__device__ hf s1b  [(size_t)BB*HH*SS*SS];
__device__ hf c2pb [(size_t)BB*HH*SS*PP];
__device__ hf p2cb [(size_t)BB*HH*SS*PP];
__device__ hf p2cTb[(size_t)BB*HH*SS*SS];

// ---------------- helpers ------------------------------------------------------
__device__ __forceinline__ uint32_t smem_u32(const void* p) {
    uint32_t a;
    asm("{ .reg .u64 t; cvta.to.shared.u64 t, %1; cvt.u32.u64 %0, t; }" : "=r"(a) : "l"(p));
    return a;
}
__device__ __forceinline__ void cpa16(uint32_t dst, const void* src) {
    asm volatile("cp.async.cg.shared.global [%0], [%1], 16;" :: "r"(dst), "l"(src));
}
__device__ __forceinline__ void cpa_commit() { asm volatile("cp.async.commit_group;" ::: "memory"); }

__device__ __forceinline__ void ldm4(uint32_t* r, uint32_t addr) {
    asm volatile("ldmatrix.sync.aligned.m8n8.x4.shared.b16 {%0,%1,%2,%3}, [%4];"
                 : "=r"(r[0]), "=r"(r[1]), "=r"(r[2]), "=r"(r[3]) : "r"(addr));
}
__device__ __forceinline__ void mma16816(float* d, const uint32_t* a, const uint32_t* b) {
    asm volatile("mma.sync.aligned.m16n8k16.row.col.f32.f16.f16.f32 "
                 "{%0,%1,%2,%3}, {%4,%5,%6,%7}, {%8,%9}, {%0,%1,%2,%3};"
                 : "+f"(d[0]), "+f"(d[1]), "+f"(d[2]), "+f"(d[3])
                 : "r"(a[0]), "r"(a[1]), "r"(a[2]), "r"(a[3]), "r"(b[0]), "r"(b[1]));
}
__device__ __forceinline__ void cvt_split(float x, hf* hi, hf* lo, size_t o) {
    hf h = __float2half(x);
    hi[o] = h;
    if (lo) lo[o] = __float2half(x - __half2float(h));
}

// ---------------- fp16 mma.sync GEMM -------------------------------------------
// C[128 x NT] tile per block. A rows [m][k], B rows [n][k] (k-contiguous).
// NP=1: single pass. NP=3: Ah*Bh + Ah*Bl + Al*Bh (split), fp32 accumulate.
// z decodes (b = z>>4, h = z&15) for batched strides.
template <int NT, int ACT, int NP>
__global__ void __launch_bounds__(256) gemm_mma(
    const hf* __restrict__ Ah, const hf* __restrict__ Al, int ldA, ll aSB, ll aSH,
    const hf* __restrict__ Bh, const hf* __restrict__ Bl, int ldB, ll bSB, ll bSH,
    float* __restrict__ C, hf* __restrict__ Chi, hf* __restrict__ Clo,
    int ldC, ll cSB, ll cSH,
    int K, const float* __restrict__ bias)
{
    constexpr int ABY = 128 * 128;          // bytes: 128 rows x 64 halfs
    constexpr int BBY = NT * 128;
    constexpr int STAGE = ABY + BBY;
    constexpr int MT = (NT == 128) ? 4 : 2;

    extern __shared__ char smem_raw[];
    uint32_t sbase = smem_u32(smem_raw);

    int tid = threadIdx.x, lane = tid & 31, wid = tid >> 5;
    int z = blockIdx.z;

    int warpM, warpN;
    if (NT == 128) { warpM = (wid & 1) * 64; warpN = (wid >> 1) * 32; }
    else           { warpM = (wid & 3) * 32; warpN = (wid >> 2) * 32; }

    const hf* Abh = Ah + (size_t)((ll)(z >> 4) * aSB + (ll)(z & 15) * aSH)
                       + (size_t)blockIdx.y * 128 * ldA;
    const hf* Abl = Al + (Abh - Ah);
    const hf* Bbh = Bh + (size_t)((ll)(z >> 4) * bSB + (ll)(z & 15) * bSH)
                       + (size_t)blockIdx.x * NT * ldB;
    const hf* Bbl = Bl + (Bbh - Bh);

    int nseg = K >> 6;
    int NC = NP * nseg;

    auto load_chunk = [&](int cn, int stage) {
        int seg = cn / nseg, cc = cn - seg * nseg;
        const hf* Ap = (seg == 2 ? Abl : Abh) + cc * 64;
        const hf* Bp = (seg == 1 ? Bbl : Bbh) + cc * 64;
        uint32_t Ad = sbase + stage * STAGE;
        uint32_t Bd = Ad + ABY;
        #pragma unroll
        for (int i = 0; i < 4; i++) {
            int idx = tid + i * 256;
            int r = idx >> 3, c = idx & 7;
            cpa16(Ad + r * 128 + ((c ^ (r & 7)) << 4), Ap + (size_t)r * ldA + c * 8);
        }
        #pragma unroll
        for (int i = 0; i < NT / 32; i++) {
            int idx = tid + i * 256;
            int r = idx >> 3, c = idx & 7;
            cpa16(Bd + r * 128 + ((c ^ (r & 7)) << 4), Bp + (size_t)r * ldB + c * 8);
        }
        cpa_commit();
    };

    float acc[MT][4][4];
    #pragma unroll
    for (int i = 0; i < MT; i++)
        #pragma unroll
        for (int j = 0; j < 4; j++)
            #pragma unroll
            for (int e = 0; e < 4; e++) acc[i][j][e] = 0.f;

    load_chunk(0, 0);
    if (NC > 1) load_chunk(1, 1);

    for (int c = 0; c < NC; c++) {
        if (c + 2 <= NC) asm volatile("cp.async.wait_group 1;" ::: "memory");
        else             asm volatile("cp.async.wait_group 0;" ::: "memory");
        __syncthreads();

        uint32_t Ab = sbase + (c & 1) * STAGE;
        uint32_t Bb = Ab + ABY;
        #pragma unroll
        for (int ks = 0; ks < 4; ks++) {
            uint32_t a[MT][4], b[4][2];
            #pragma unroll
            for (int i = 0; i < MT; i++) {
                int row = warpM + i * 16 + (lane & 15);
                int cc = ks * 2 + (lane >> 4);
                ldm4(a[i], Ab + row * 128 + (((cc ^ (row & 7)) << 4)));
            }
            #pragma unroll
            for (int j = 0; j < 2; j++) {
                int n = warpN + j * 16 + ((lane >> 4) << 3) + (lane & 7);
                int cc = ks * 2 + ((lane >> 3) & 1);
                uint32_t t[4];
                ldm4(t, Bb + n * 128 + (((cc ^ (n & 7)) << 4)));
                b[j*2][0] = t[0];   b[j*2][1] = t[1];
                b[j*2+1][0] = t[2]; b[j*2+1][1] = t[3];
            }
            #pragma unroll
            for (int i = 0; i < MT; i++)
                #pragma unroll
                for (int j = 0; j < 4; j++)
                    mma16816(acc[i][j], a[i], b[j]);
        }
        __syncthreads();
        if (c + 2 < NC) load_chunk(c + 2, c & 1);
    }

    // ---- epilogue ----
    ll cO = (ll)(z >> 4) * cSB + (ll)(z & 15) * cSH;
    int m0 = blockIdx.y * 128, n0 = blockIdx.x * NT;
    int quad = lane >> 2, l4 = lane & 3;

    #pragma unroll
    for (int i = 0; i < MT; i++) {
        int r0 = m0 + warpM + i * 16 + quad;
        #pragma unroll
        for (int j = 0; j < 4; j++) {
            int col = n0 + warpN + j * 8 + l4 * 2;
            float b0 = 0.f, b1 = 0.f;
            if (bias) { b0 = bias[col]; b1 = bias[col + 1]; }
            #pragma unroll
            for (int half = 0; half < 2; half++) {
                int row = r0 + half * 8;
                float v0 = acc[i][j][half*2 + 0] + b0;
                float v1 = acc[i][j][half*2 + 1] + b1;
                if (ACT) {
                    v0 = 0.5f * v0 * (1.f + erff(v0 * 0.70710678118654752f));
                    v1 = 0.5f * v1 * (1.f + erff(v1 * 0.70710678118654752f));
                }
                size_t base = (size_t)cO + (size_t)row * ldC + col;
                if (C) *(float2*)(C + base) = make_float2(v0, v1);
                if (Chi) {
                    hf h0 = __float2half(v0);
                    hf h1 = __float2half(v1);
                    *(__half2*)(Chi + base) = __halves2half2(h0, h1);
                    if (Clo) {
                        hf l0 = __float2half(v0 - __half2float(h0));
                        hf l1 = __float2half(v1 - __half2float(h1));
                        *(__half2*)(Clo + base) = __halves2half2(l0, l1);
                    }
                }
            }
        }
    }
}

// ---------------- converters -----------------------------------------------------
__global__ __launch_bounds__(256) void split_cvt(
    const float* __restrict__ in, hf* __restrict__ hi, hf* __restrict__ lo, size_t n)
{
    for (size_t i = blockIdx.x * 256ull + threadIdx.x; i < n; i += gridDim.x * 256ull)
        cvt_split(in[i], hi, lo, i);
}

// in [K x N] fp32 -> out [N x K] fp16 hi/lo
__global__ void transpose_split(
    const float* __restrict__ in, hf* __restrict__ hi, hf* __restrict__ lo,
    int K, int N)
{
    __shared__ float t[32][33];
    int k0 = blockIdx.y * 32, n0 = blockIdx.x * 32;
    int tx = threadIdx.x, ty = threadIdx.y;
    for (int i = ty; i < 32; i += 8)
        t[i][tx] = in[(size_t)(k0 + i) * N + n0 + tx];
    __syncthreads();
    for (int i = ty; i < 32; i += 8)
        cvt_split(t[tx][i], hi, lo, (size_t)(n0 + i) * K + k0 + tx);
}

// v fp16 [b][s][h*64+d] -> vt fp16 [(b*16+h)*64+d][s]
__global__ void vt_cvt(const hf* __restrict__ v, hf* __restrict__ out)
{
    __shared__ hf t[32][33];
    int bh = blockIdx.z, b = bh >> 4, h = bh & 15;
    int s0 = blockIdx.x * 32, d0 = blockIdx.y * 32;
    int tx = threadIdx.x, ty = threadIdx.y;
    for (int i = ty; i < 32; i += 8)
        t[i][tx] = v[((size_t)b * SS + s0 + i) * DD + h * 64 + d0 + tx];
    __syncthreads();
    for (int i = ty; i < 32; i += 8)
        out[((size_t)bh * 64 + d0 + i) * SS + s0 + tx] = t[tx][i];
}

// p2cT[bh][q][k] = p2c[bh][k][clip(q-k+512,0,1023)]
__global__ void p2c_remap(const hf* __restrict__ p2c, hf* __restrict__ out)
{
    __shared__ hf t[64][34];
    int bh = blockIdx.z;
    int q0 = blockIdx.y * 32, k0 = blockIdx.x * 32;
    int tx = threadIdx.x, ty = threadIdx.y;
    int base = q0 - k0 + SPAN_ - 31;
    const hf* src = p2c + (size_t)bh * SS * PP;
    for (int kk = ty; kk < 32; kk += 8) {
        int row = k0 + kk;
        int c0 = min(max(base + tx, 0), PP - 1);
        int c1 = min(max(base + tx + 32, 0), PP - 1);
        t[tx][kk]      = src[(size_t)row * PP + c0];
        t[tx + 32][kk] = src[(size_t)row * PP + c1];
    }
    __syncthreads();
    hf* dst = out + (size_t)bh * SS * SS;
    for (int qq = ty; qq < 32; qq += 8)
        dst[(size_t)(q0 + qq) * SS + k0 + tx] = t[qq + 31 - tx][tx];
}

// ---------------- embedding / LN / softmax ----------------------------------------
__global__ __launch_bounds__(256) void embed_ln(
    const int* __restrict__ ids, const int* __restrict__ segs,
    const float* __restrict__ mask, const float* __restrict__ tok,
    const float* __restrict__ seg, const float* __restrict__ g,
    const float* __restrict__ b)
{
    int row = blockIdx.x, tid = threadIdx.x;
    const float* t  = tok + (size_t)ids[row]  * DD;
    const float* sg = seg + (size_t)segs[row] * DD;
    float x[4]; float s = 0.f;
    #pragma unroll
    for (int i = 0; i < 4; i++) { int c = tid + i*256; x[i] = t[c] + sg[c]; s += x[i]; }
    __shared__ float red[256];
    red[tid] = s; __syncthreads();
    for (int o = 128; o > 0; o >>= 1) { if (tid < o) red[tid] += red[tid+o]; __syncthreads(); }
    float m = red[0] * (1.f / DD); __syncthreads();
    s = 0.f;
    #pragma unroll
    for (int i = 0; i < 4; i++) { float d = x[i] - m; s += d*d; }
    red[tid] = s; __syncthreads();
    for (int o = 128; o > 0; o >>= 1) { if (tid < o) red[tid] += red[tid+o]; __syncthreads(); }
    float inv = rsqrtf(red[0] * (1.f / DD) + 1e-12f);
    float mk = mask[row];
    #pragma unroll
    for (int i = 0; i < 4; i++) {
        int c = tid + i*256;
        float y = ((x[i] - m) * inv * g[c] + b[c]) * mk;
        size_t o = (size_t)row * DD + c;
        g_h[o] = y; cvt_split(y, hb_hi, hb_lo, o);
    }
}

__global__ __launch_bounds__(256) void add_ln(
    const float* __restrict__ base, const float* __restrict__ addv,
    const float* __restrict__ g, const float* __restrict__ b,
    float* __restrict__ out)
{
    int row = blockIdx.x, tid = threadIdx.x;
    size_t off = (size_t)row * DD;
    float x[4]; float s = 0.f;
    #pragma unroll
    for (int i = 0; i < 4; i++) { int c = tid + i*256; x[i] = base[off+c] + addv[off+c]; s += x[i]; }
    __shared__ float red[256];
    red[tid] = s; __syncthreads();
    for (int o = 128; o > 0; o >>= 1) { if (tid < o) red[tid] += red[tid+o]; __syncthreads(); }
    float m = red[0] * (1.f / DD); __syncthreads();
    s = 0.f;
    #pragma unroll
    for (int i = 0; i < 4; i++) { float d = x[i] - m; s += d*d; }
    red[tid] = s; __syncthreads();
    for (int o = 128; o > 0; o >>= 1) { if (tid < o) red[tid] += red[tid+o]; __syncthreads(); }
    float inv = rsqrtf(red[0] * (1.f / DD) + 1e-12f);
    #pragma unroll
    for (int i = 0; i < 4; i++) {
        int c = tid + i*256;
        float y = (x[i] - m) * inv * g[c] + b[c];
        out[off + c] = y; cvt_split(y, hb_hi, hb_lo, off + c);
    }
}

__global__ __launch_bounds__(256) void softmax_rel(
    const hf* __restrict__ att, const hf* __restrict__ c2p,
    const hf* __restrict__ p2cT, const float* __restrict__ mask)
{
    int bh = blockIdx.y, q = blockIdx.x, b = bh / HH;
    int tid = threadIdx.x;
    size_t rowOff = ((size_t)bh * SS + q) * SS;
    const float scale = 0.07216878364870323f; // 1/sqrt(64*3)

    float v[4];
    #pragma unroll
    for (int t = 0; t < 4; t++) {
        int k = tid + t * 256;
        int idx = min(max(q - k + SPAN_, 0), PP - 1);
        float s = __half2float(att[rowOff + k])
                + __half2float(c2p[((size_t)bh * SS + q) * PP + idx])
                + __half2float(p2cT[rowOff + k]);
        v[t] = s * scale + (1.f - mask[b * SS + k]) * -1e9f;
    }
    __shared__ float red[256];
    float m = fmaxf(fmaxf(v[0], v[1]), fmaxf(v[2], v[3]));
    red[tid] = m; __syncthreads();
    for (int o = 128; o > 0; o >>= 1) { if (tid < o) red[tid] = fmaxf(red[tid], red[tid+o]); __syncthreads(); }
    m = red[0]; __syncthreads();
    float s = 0.f;
    #pragma unroll
    for (int t = 0; t < 4; t++) { v[t] = expf(v[t] - m); s += v[t]; }
    red[tid] = s; __syncthreads();
    for (int o = 128; o > 0; o >>= 1) { if (tid < o) red[tid] += red[tid+o]; __syncthreads(); }
    float inv = 1.f / red[0];
    #pragma unroll
    for (int t = 0; t < 4; t++)
        prb[rowOff + tid + t * 256] = __float2half(v[t] * inv);
}

// ---------------- host --------------------------------------------------------------
extern "C" void kernel_launch(void* const* d_in, const int* in_sizes, int n_in,
                              void* d_out, int out_size)
{
    const int*   ids  = (const int*)d_in[0];
    const int*   segs = (const int*)d_in[1];
    const float* mask = (const float*)d_in[2];
    const float* tok  = (const float*)d_in[3];
    const float* seg  = (const float*)d_in[4];
    const float* elg  = (const float*)d_in[5];
    const float* elb  = (const float*)d_in[6];
    const float* rel  = (const float*)d_in[7];
    const float* Wq = (const float*)d_in[8],  *bq = (const float*)d_in[9];
    const float* Wk = (const float*)d_in[10], *bk = (const float*)d_in[11];
    const float* Wv = (const float*)d_in[12], *bv = (const float*)d_in[13];
    const float* Wo = (const float*)d_in[14], *bo = (const float*)d_in[15];
    const float* l1g = (const float*)d_in[16], *l1b = (const float*)d_in[17];
    const float* W1 = (const float*)d_in[18], *b1 = (const float*)d_in[19];
    const float* W2 = (const float*)d_in[20], *b2 = (const float*)d_in[21];
    const float* l2g = (const float*)d_in[22], *l2b = (const float*)d_in[23];

    float *h, *t2;
    cudaGetSymbolAddress((void**)&h,  g_h);
    cudaGetSymbolAddress((void**)&t2, g_t2);

    hf *hH,*hL,*q,*k,*v,*cxH,*cxL,*fH,*fL,*rlH,*rlL,*pk,*pq;
    hf *wqH,*wqL,*wkH,*wkL,*wvH,*wvL,*woH,*woL,*w1H,*w1L,*w2H,*w2L;
    hf *vt,*pr,*s1,*c2p,*p2c,*p2cT;
    cudaGetSymbolAddress((void**)&hH, hb_hi);   cudaGetSymbolAddress((void**)&hL, hb_lo);
    cudaGetSymbolAddress((void**)&q,  qb);      cudaGetSymbolAddress((void**)&k,  kb);
    cudaGetSymbolAddress((void**)&v,  vb);
    cudaGetSymbolAddress((void**)&cxH, cx_hi);  cudaGetSymbolAddress((void**)&cxL, cx_lo);
    cudaGetSymbolAddress((void**)&fH, ff_hi);   cudaGetSymbolAddress((void**)&fL, ff_lo);
    cudaGetSymbolAddress((void**)&rlH, rl_hi);  cudaGetSymbolAddress((void**)&rlL, rl_lo);
    cudaGetSymbolAddress((void**)&pk, pkb);     cudaGetSymbolAddress((void**)&pq, pqb);
    cudaGetSymbolAddress((void**)&wqH, wqt_hi); cudaGetSymbolAddress((void**)&wqL, wqt_lo);
    cudaGetSymbolAddress((void**)&wkH, wkt_hi); cudaGetSymbolAddress((void**)&wkL, wkt_lo);
    cudaGetSymbolAddress((void**)&wvH, wvt_hi); cudaGetSymbolAddress((void**)&wvL, wvt_lo);
    cudaGetSymbolAddress((void**)&woH, wot_hi); cudaGetSymbolAddress((void**)&woL, wot_lo);
    cudaGetSymbolAddress((void**)&w1H, w1t_hi); cudaGetSymbolAddress((void**)&w1L, w1t_lo);
    cudaGetSymbolAddress((void**)&w2H, w2t_hi); cudaGetSymbolAddress((void**)&w2L, w2t_lo);
    cudaGetSymbolAddress((void**)&vt, vtb);     cudaGetSymbolAddress((void**)&pr, prb);
    cudaGetSymbolAddress((void**)&s1, s1b);     cudaGetSymbolAddress((void**)&c2p, c2pb);
    cudaGetSymbolAddress((void**)&p2c, p2cb);   cudaGetSymbolAddress((void**)&p2cT, p2cTb);

    const int SM128 = 2 * (128*128 + 128*128);   // 65536
    const int SM64  = 2 * (128*128 + 64*128);    // 49152
    cudaFuncSetAttribute(gemm_mma<128,0,1>, cudaFuncAttributeMaxDynamicSharedMemorySize, SM128);
    cudaFuncSetAttribute(gemm_mma<128,0,3>, cudaFuncAttributeMaxDynamicSharedMemorySize, SM128);
    cudaFuncSetAttribute(gemm_mma<128,1,3>, cudaFuncAttributeMaxDynamicSharedMemorySize, SM128);
    cudaFuncSetAttribute(gemm_mma<64,0,1>,  cudaFuncAttributeMaxDynamicSharedMemorySize, SM64);

    embed_ln<<<BS, 256>>>(ids, segs, mask, tok, seg, elg, elb);
    split_cvt<<<512, 256>>>(rel, rlH, rlL, (size_t)PP * DD);

    dim3 tb(32, 8);
    const ll S2 = (ll)SS * SS;
    const ll SD = (ll)SS * DD;

    for (int l = 0; l < LL; l++) {
        const float* wq = Wq + (size_t)l*DD*DD;  const float* bq_ = bq + (size_t)l*DD;
        const float* wk = Wk + (size_t)l*DD*DD;  const float* bk_ = bk + (size_t)l*DD;
        const float* wv = Wv + (size_t)l*DD*DD;  const float* bv_ = bv + (size_t)l*DD;
        const float* wo = Wo + (size_t)l*DD*DD;  const float* bo_ = bo + (size_t)l*DD;
        const float* w1 = W1 + (size_t)l*DD*FFD; const float* b1_ = b1 + (size_t)l*FFD;
        const float* w2 = W2 + (size_t)l*FFD*DD; const float* b2_ = b2 + (size_t)l*DD;
        const float* g1 = l1g + (size_t)l*DD;    const float* be1 = l1b + (size_t)l*DD;
        const float* g2 = l2g + (size_t)l*DD;    const float* be2 = l2b + (size_t)l*DD;

        transpose_split<<<dim3(32, 32),  tb>>>(wq, wqH, wqL, DD, DD);
        transpose_split<<<dim3(32, 32),  tb>>>(wk, wkH, wkL, DD, DD);
        transpose_split<<<dim3(32, 32),  tb>>>(wv, wvH, wvL, DD, DD);
        transpose_split<<<dim3(32, 32),  tb>>>(wo, woH, woL, DD, DD);
        transpose_split<<<dim3(128, 32), tb>>>(w1, w1H, w1L, DD, FFD);
        transpose_split<<<dim3(32, 128), tb>>>(w2, w2H, w2L, FFD, DD);

        // projections (split, 3-pass)
        gemm_mma<128,0,3><<<dim3(8,32,1), 256, SM128>>>(hH,hL,DD,0,0, wqH,wqL,DD,0,0,
            (float*)0, q, (hf*)0, DD,0,0, DD, bq_);
        gemm_mma<128,0,3><<<dim3(8,32,1), 256, SM128>>>(hH,hL,DD,0,0, wkH,wkL,DD,0,0,
            (float*)0, k, (hf*)0, DD,0,0, DD, bk_);
        gemm_mma<128,0,3><<<dim3(8,32,1), 256, SM128>>>(hH,hL,DD,0,0, wvH,wvL,DD,0,0,
            (float*)0, v, (hf*)0, DD,0,0, DD, bv_);
        gemm_mma<128,0,3><<<dim3(8,8,1),  256, SM128>>>(rlH,rlL,DD,0,0, wkH,wkL,DD,0,0,
            (float*)0, pk, (hf*)0, DD,0,0, DD, bk_);
        gemm_mma<128,0,3><<<dim3(8,8,1),  256, SM128>>>(rlH,rlL,DD,0,0, wqH,wqL,DD,0,0,
            (float*)0, pq, (hf*)0, DD,0,0, DD, bq_);

        // attention scores (single-pass fp16)
        gemm_mma<128,0,1><<<dim3(8,8,64), 256, SM128>>>(q,q,DD,SD,64, k,k,DD,SD,64,
            (float*)0, s1, (hf*)0, SS,16*S2,S2, 64, (const float*)0);
        gemm_mma<128,0,1><<<dim3(8,8,64), 256, SM128>>>(q,q,DD,SD,64, pk,pk,DD,0,64,
            (float*)0, c2p, (hf*)0, PP,16*S2,S2, 64, (const float*)0);
        gemm_mma<128,0,1><<<dim3(8,8,64), 256, SM128>>>(k,k,DD,SD,64, pq,pq,DD,0,64,
            (float*)0, p2c, (hf*)0, PP,16*S2,S2, 64, (const float*)0);

        p2c_remap<<<dim3(32,32,64), tb>>>(p2c, p2cT);
        softmax_rel<<<dim3(SS, 64), 256>>>(s1, c2p, p2cT, mask);
        vt_cvt<<<dim3(32,2,64), tb>>>(v, vt);

        // ctx = probs @ V (single-pass; output split for O-proj)
        gemm_mma<64,0,1><<<dim3(1,8,64), 256, SM64>>>(pr,pr,SS,16*S2,S2, vt,vt,SS,(ll)16*64*SS,(ll)64*SS,
            (float*)0, cxH, cxL, DD,SD,64, SS, (const float*)0);

        // output projection (split) + LN
        gemm_mma<128,0,3><<<dim3(8,32,1), 256, SM128>>>(cxH,cxL,DD,0,0, woH,woL,DD,0,0,
            t2, (hf*)0, (hf*)0, DD,0,0, DD, bo_);
        add_ln<<<BS, 256>>>(h, t2, g1, be1, h);

        // FFN (split)
        gemm_mma<128,1,3><<<dim3(32,32,1), 256, SM128>>>(hH,hL,DD,0,0, w1H,w1L,DD,0,0,
            (float*)0, fH, fL, FFD,0,0, DD, b1_);
        gemm_mma<128,0,3><<<dim3(8,32,1), 256, SM128>>>(fH,fL,FFD,0,0, w2H,w2L,FFD,0,0,
            t2, (hf*)0, (hf*)0, DD,0,0, FFD, b2_);
        add_ln<<<BS, 256>>>(h, t2, g2, be2, h);
    }

    cudaMemcpyAsync(d_out, h, (size_t)BS * DD * sizeof(float),
                    cudaMemcpyDeviceToDevice);
}

// round 6
// speedup vs baseline: 4.7710x; 1.6826x over previous
#include <cuda_runtime.h>
#include <cuda_fp16.h>
#include <math.h>
#include <stdint.h>

#define BB 4
#define SS 1024
#define DD 1024
#define HH 16
#define DHH 64
#define FFD 4096
#define LL 4
#define PP 1024
#define SPAN_ 512
#define BS (BB*SS)

typedef long long ll;
typedef __half hf;

// ---------------- scratch ------------------------------------------------------
__device__ float g_h [BS*DD];
__device__ float g_t2[BS*DD];

__device__ hf hb   [BS*DD];
__device__ hf qb   [BS*DD];
__device__ hf kb   [BS*DD];
__device__ hf vb   [BS*DD];
__device__ hf cxb  [BS*DD];
__device__ hf ffb  [(size_t)BS*FFD];
__device__ hf rlb  [PP*DD];
__device__ hf pkb  [PP*DD];
__device__ hf pqb  [PP*DD];
__device__ hf wqt  [DD*DD];
__device__ hf wkt  [DD*DD];
__device__ hf wvt  [DD*DD];
__device__ hf wot  [DD*DD];
__device__ hf w1t  [(size_t)FFD*DD];
__device__ hf w2t  [(size_t)DD*FFD];
__device__ hf vtb  [(size_t)BB*HH*DHH*SS];
__device__ hf prb  [(size_t)BB*HH*SS*SS];
__device__ hf s1b  [(size_t)BB*HH*SS*SS];
__device__ hf c2pb [(size_t)BB*HH*SS*PP];
__device__ hf p2cb [(size_t)BB*HH*SS*PP];
__device__ hf p2cTb[(size_t)BB*HH*SS*SS];

// ---------------- helpers ------------------------------------------------------
__device__ __forceinline__ uint32_t smem_u32(const void* p) {
    uint32_t a;
    asm("{ .reg .u64 t; cvta.to.shared.u64 t, %1; cvt.u32.u64 %0, t; }" : "=r"(a) : "l"(p));
    return a;
}
__device__ __forceinline__ void cpa16(uint32_t dst, const void* src) {
    asm volatile("cp.async.cg.shared.global [%0], [%1], 16;" :: "r"(dst), "l"(src));
}
__device__ __forceinline__ void cpa_commit() { asm volatile("cp.async.commit_group;" ::: "memory"); }

__device__ __forceinline__ void ldm4(uint32_t* r, uint32_t addr) {
    asm volatile("ldmatrix.sync.aligned.m8n8.x4.shared.b16 {%0,%1,%2,%3}, [%4];"
                 : "=r"(r[0]), "=r"(r[1]), "=r"(r[2]), "=r"(r[3]) : "r"(addr));
}
__device__ __forceinline__ void mma16816(float* d, const uint32_t* a, const uint32_t* b) {
    asm volatile("mma.sync.aligned.m16n8k16.row.col.f32.f16.f16.f32 "
                 "{%0,%1,%2,%3}, {%4,%5,%6,%7}, {%8,%9}, {%0,%1,%2,%3};"
                 : "+f"(d[0]), "+f"(d[1]), "+f"(d[2]), "+f"(d[3])
                 : "r"(a[0]), "r"(a[1]), "r"(a[2]), "r"(a[3]), "r"(b[0]), "r"(b[1]));
}

// ---------------- fp16 mma.sync GEMM (single-pass) ------------------------------
// C[128 x NT] tile per block. A rows [m][k], B rows [n][k] (k-contiguous).
// z decodes (b = z>>4, h = z&15) for batched strides.
template <int NT, int ACT>
__global__ void __launch_bounds__(256) gemm_mma(
    const hf* __restrict__ A, int ldA, ll aSB, ll aSH,
    const hf* __restrict__ B, int ldB, ll bSB, ll bSH,
    float* __restrict__ C, hf* __restrict__ Ch,
    int ldC, ll cSB, ll cSH,
    int K, const float* __restrict__ bias)
{
    constexpr int ABY = 128 * 128;          // bytes: 128 rows x 64 halfs
    constexpr int BBY = NT * 128;
    constexpr int STAGE = ABY + BBY;
    constexpr int MT = (NT == 128) ? 4 : 2;

    extern __shared__ char smem_raw[];
    uint32_t sbase = smem_u32(smem_raw);

    int tid = threadIdx.x, lane = tid & 31, wid = tid >> 5;
    int z = blockIdx.z;

    int warpM, warpN;
    if (NT == 128) { warpM = (wid & 1) * 64; warpN = (wid >> 1) * 32; }
    else           { warpM = (wid & 3) * 32; warpN = (wid >> 2) * 32; }

    const hf* Ab = A + (size_t)((ll)(z >> 4) * aSB + (ll)(z & 15) * aSH)
                     + (size_t)blockIdx.y * 128 * ldA;
    const hf* Bb = B + (size_t)((ll)(z >> 4) * bSB + (ll)(z & 15) * bSH)
                     + (size_t)blockIdx.x * NT * ldB;

    int NC = K >> 6;

    auto load_chunk = [&](int cn, int stage) {
        const hf* Ap = Ab + cn * 64;
        const hf* Bp = Bb + cn * 64;
        uint32_t Ad = sbase + stage * STAGE;
        uint32_t Bd = Ad + ABY;
        #pragma unroll
        for (int i = 0; i < 4; i++) {
            int idx = tid + i * 256;
            int r = idx >> 3, c = idx & 7;
            cpa16(Ad + r * 128 + ((c ^ (r & 7)) << 4), Ap + (size_t)r * ldA + c * 8);
        }
        #pragma unroll
        for (int i = 0; i < NT / 32; i++) {
            int idx = tid + i * 256;
            int r = idx >> 3, c = idx & 7;
            cpa16(Bd + r * 128 + ((c ^ (r & 7)) << 4), Bp + (size_t)r * ldB + c * 8);
        }
        cpa_commit();
    };

    float acc[MT][4][4];
    #pragma unroll
    for (int i = 0; i < MT; i++)
        #pragma unroll
        for (int j = 0; j < 4; j++)
            #pragma unroll
            for (int e = 0; e < 4; e++) acc[i][j][e] = 0.f;

    load_chunk(0, 0);
    if (NC > 1) load_chunk(1, 1);

    for (int c = 0; c < NC; c++) {
        if (c + 2 <= NC) asm volatile("cp.async.wait_group 1;" ::: "memory");
        else             asm volatile("cp.async.wait_group 0;" ::: "memory");
        __syncthreads();

        uint32_t Abuf = sbase + (c & 1) * STAGE;
        uint32_t Bbuf = Abuf + ABY;
        #pragma unroll
        for (int ks = 0; ks < 4; ks++) {
            uint32_t a[MT][4], b[4][2];
            #pragma unroll
            for (int i = 0; i < MT; i++) {
                int row = warpM + i * 16 + (lane & 15);
                int cc = ks * 2 + (lane >> 4);
                ldm4(a[i], Abuf + row * 128 + (((cc ^ (row & 7)) << 4)));
            }
            #pragma unroll
            for (int j = 0; j < 2; j++) {
                int n = warpN + j * 16 + ((lane >> 4) << 3) + (lane & 7);
                int cc = ks * 2 + ((lane >> 3) & 1);
                uint32_t t[4];
                ldm4(t, Bbuf + n * 128 + (((cc ^ (n & 7)) << 4)));
                b[j*2][0] = t[0];   b[j*2][1] = t[1];
                b[j*2+1][0] = t[2]; b[j*2+1][1] = t[3];
            }
            #pragma unroll
            for (int i = 0; i < MT; i++)
                #pragma unroll
                for (int j = 0; j < 4; j++)
                    mma16816(acc[i][j], a[i], b[j]);
        }
        __syncthreads();
        if (c + 2 < NC) load_chunk(c + 2, c & 1);
    }

    // ---- epilogue ----
    ll cO = (ll)(z >> 4) * cSB + (ll)(z & 15) * cSH;
    int m0 = blockIdx.y * 128, n0 = blockIdx.x * NT;
    int quad = lane >> 2, l4 = lane & 3;

    #pragma unroll
    for (int i = 0; i < MT; i++) {
        int r0 = m0 + warpM + i * 16 + quad;
        #pragma unroll
        for (int j = 0; j < 4; j++) {
            int col = n0 + warpN + j * 8 + l4 * 2;
            float b0 = 0.f, b1 = 0.f;
            if (bias) { b0 = bias[col]; b1 = bias[col + 1]; }
            #pragma unroll
            for (int half = 0; half < 2; half++) {
                int row = r0 + half * 8;
                float v0 = acc[i][j][half*2 + 0] + b0;
                float v1 = acc[i][j][half*2 + 1] + b1;
                if (ACT) {
                    v0 = 0.5f * v0 * (1.f + erff(v0 * 0.70710678118654752f));
                    v1 = 0.5f * v1 * (1.f + erff(v1 * 0.70710678118654752f));
                }
                size_t base = (size_t)cO + (size_t)row * ldC + col;
                if (C) *(float2*)(C + base) = make_float2(v0, v1);
                if (Ch) *(__half2*)(Ch + base) =
                    __halves2half2(__float2half(v0), __float2half(v1));
            }
        }
    }
}

// ---------------- converters -----------------------------------------------------
__global__ __launch_bounds__(256) void cvt_fp16(
    const float* __restrict__ in, hf* __restrict__ out, size_t n)
{
    for (size_t i = blockIdx.x * 256ull + threadIdx.x; i < n; i += gridDim.x * 256ull)
        out[i] = __float2half(in[i]);
}

// in [K x N] fp32 -> out [N x K] fp16
__global__ void transpose_cvt(
    const float* __restrict__ in, hf* __restrict__ out, int K, int N)
{
    __shared__ float t[32][33];
    int k0 = blockIdx.y * 32, n0 = blockIdx.x * 32;
    int tx = threadIdx.x, ty = threadIdx.y;
    for (int i = ty; i < 32; i += 8)
        t[i][tx] = in[(size_t)(k0 + i) * N + n0 + tx];
    __syncthreads();
    for (int i = ty; i < 32; i += 8)
        out[(size_t)(n0 + i) * K + k0 + tx] = __float2half(t[tx][i]);
}

// v fp16 [b][s][h*64+d] -> vt fp16 [(b*16+h)*64+d][s]
__global__ void vt_cvt(const hf* __restrict__ v, hf* __restrict__ out)
{
    __shared__ hf t[32][33];
    int bh = blockIdx.z, b = bh >> 4, h = bh & 15;
    int s0 = blockIdx.x * 32, d0 = blockIdx.y * 32;
    int tx = threadIdx.x, ty = threadIdx.y;
    for (int i = ty; i < 32; i += 8)
        t[i][tx] = v[((size_t)b * SS + s0 + i) * DD + h * 64 + d0 + tx];
    __syncthreads();
    for (int i = ty; i < 32; i += 8)
        out[((size_t)bh * 64 + d0 + i) * SS + s0 + tx] = t[tx][i];
}

// p2cT[bh][q][k] = p2c[bh][k][clip(q-k+512,0,1023)]
__global__ void p2c_remap(const hf* __restrict__ p2c, hf* __restrict__ out)
{
    __shared__ hf t[64][34];
    int bh = blockIdx.z;
    int q0 = blockIdx.y * 32, k0 = blockIdx.x * 32;
    int tx = threadIdx.x, ty = threadIdx.y;
    int base = q0 - k0 + SPAN_ - 31;
    const hf* src = p2c + (size_t)bh * SS * PP;
    for (int kk = ty; kk < 32; kk += 8) {
        int row = k0 + kk;
        int c0 = min(max(base + tx, 0), PP - 1);
        int c1 = min(max(base + tx + 32, 0), PP - 1);
        t[tx][kk]      = src[(size_t)row * PP + c0];
        t[tx + 32][kk] = src[(size_t)row * PP + c1];
    }
    __syncthreads();
    hf* dst = out + (size_t)bh * SS * SS;
    for (int qq = ty; qq < 32; qq += 8)
        dst[(size_t)(q0 + qq) * SS + k0 + tx] = t[qq + 31 - tx][tx];
}

// ---------------- embedding / LN / softmax ----------------------------------------
__global__ __launch_bounds__(256) void embed_ln(
    const int* __restrict__ ids, const int* __restrict__ segs,
    const float* __restrict__ mask, const float* __restrict__ tok,
    const float* __restrict__ seg, const float* __restrict__ g,
    const float* __restrict__ b)
{
    int row = blockIdx.x, tid = threadIdx.x;
    const float* t  = tok + (size_t)ids[row]  * DD;
    const float* sg = seg + (size_t)segs[row] * DD;
    float x[4]; float s = 0.f;
    #pragma unroll
    for (int i = 0; i < 4; i++) { int c = tid + i*256; x[i] = t[c] + sg[c]; s += x[i]; }
    __shared__ float red[256];
    red[tid] = s; __syncthreads();
    for (int o = 128; o > 0; o >>= 1) { if (tid < o) red[tid] += red[tid+o]; __syncthreads(); }
    float m = red[0] * (1.f / DD); __syncthreads();
    s = 0.f;
    #pragma unroll
    for (int i = 0; i < 4; i++) { float d = x[i] - m; s += d*d; }
    red[tid] = s; __syncthreads();
    for (int o = 128; o > 0; o >>= 1) { if (tid < o) red[tid] += red[tid+o]; __syncthreads(); }
    float inv = rsqrtf(red[0] * (1.f / DD) + 1e-12f);
    float mk = mask[row];
    #pragma unroll
    for (int i = 0; i < 4; i++) {
        int c = tid + i*256;
        float y = ((x[i] - m) * inv * g[c] + b[c]) * mk;
        size_t o = (size_t)row * DD + c;
        g_h[o] = y; hb[o] = __float2half(y);
    }
}

__global__ __launch_bounds__(256) void add_ln(
    const float* __restrict__ base, const float* __restrict__ addv,
    const float* __restrict__ g, const float* __restrict__ b,
    float* __restrict__ out)
{
    int row = blockIdx.x, tid = threadIdx.x;
    size_t off = (size_t)row * DD;
    float x[4]; float s = 0.f;
    #pragma unroll
    for (int i = 0; i < 4; i++) { int c = tid + i*256; x[i] = base[off+c] + addv[off+c]; s += x[i]; }
    __shared__ float red[256];
    red[tid] = s; __syncthreads();
    for (int o = 128; o > 0; o >>= 1) { if (tid < o) red[tid] += red[tid+o]; __syncthreads(); }
    float m = red[0] * (1.f / DD); __syncthreads();
    s = 0.f;
    #pragma unroll
    for (int i = 0; i < 4; i++) { float d = x[i] - m; s += d*d; }
    red[tid] = s; __syncthreads();
    for (int o = 128; o > 0; o >>= 1) { if (tid < o) red[tid] += red[tid+o]; __syncthreads(); }
    float inv = rsqrtf(red[0] * (1.f / DD) + 1e-12f);
    #pragma unroll
    for (int i = 0; i < 4; i++) {
        int c = tid + i*256;
        float y = (x[i] - m) * inv * g[c] + b[c];
        out[off + c] = y; hb[off + c] = __float2half(y);
    }
}

__global__ __launch_bounds__(256) void softmax_rel(
    const hf* __restrict__ att, const hf* __restrict__ c2p,
    const hf* __restrict__ p2cT, const float* __restrict__ mask)
{
    int bh = blockIdx.y, q = blockIdx.x, b = bh / HH;
    int tid = threadIdx.x;
    size_t rowOff = ((size_t)bh * SS + q) * SS;
    const float scale = 0.07216878364870323f; // 1/sqrt(64*3)

    float v[4];
    #pragma unroll
    for (int t = 0; t < 4; t++) {
        int k = tid + t * 256;
        int idx = min(max(q - k + SPAN_, 0), PP - 1);
        float s = __half2float(att[rowOff + k])
                + __half2float(c2p[((size_t)bh * SS + q) * PP + idx])
                + __half2float(p2cT[rowOff + k]);
        v[t] = s * scale + (1.f - mask[b * SS + k]) * -1e9f;
    }
    __shared__ float red[256];
    float m = fmaxf(fmaxf(v[0], v[1]), fmaxf(v[2], v[3]));
    red[tid] = m; __syncthreads();
    for (int o = 128; o > 0; o >>= 1) { if (tid < o) red[tid] = fmaxf(red[tid], red[tid+o]); __syncthreads(); }
    m = red[0]; __syncthreads();
    float s = 0.f;
    #pragma unroll
    for (int t = 0; t < 4; t++) { v[t] = expf(v[t] - m); s += v[t]; }
    red[tid] = s; __syncthreads();
    for (int o = 128; o > 0; o >>= 1) { if (tid < o) red[tid] += red[tid+o]; __syncthreads(); }
    float inv = 1.f / red[0];
    #pragma unroll
    for (int t = 0; t < 4; t++)
        prb[rowOff + tid + t * 256] = __float2half(v[t] * inv);
}

// ---------------- host --------------------------------------------------------------
extern "C" void kernel_launch(void* const* d_in, const int* in_sizes, int n_in,
                              void* d_out, int out_size)
{
    const int*   ids  = (const int*)d_in[0];
    const int*   segs = (const int*)d_in[1];
    const float* mask = (const float*)d_in[2];
    const float* tok  = (const float*)d_in[3];
    const float* seg  = (const float*)d_in[4];
    const float* elg  = (const float*)d_in[5];
    const float* elb  = (const float*)d_in[6];
    const float* rel  = (const float*)d_in[7];
    const float* Wq = (const float*)d_in[8],  *bq = (const float*)d_in[9];
    const float* Wk = (const float*)d_in[10], *bk = (const float*)d_in[11];
    const float* Wv = (const float*)d_in[12], *bv = (const float*)d_in[13];
    const float* Wo = (const float*)d_in[14], *bo = (const float*)d_in[15];
    const float* l1g = (const float*)d_in[16], *l1b = (const float*)d_in[17];
    const float* W1 = (const float*)d_in[18], *b1 = (const float*)d_in[19];
    const float* W2 = (const float*)d_in[20], *b2 = (const float*)d_in[21];
    const float* l2g = (const float*)d_in[22], *l2b = (const float*)d_in[23];

    float *h, *t2;
    cudaGetSymbolAddress((void**)&h,  g_h);
    cudaGetSymbolAddress((void**)&t2, g_t2);

    hf *hh,*q,*k,*v,*cx,*ff,*rl,*pk,*pq;
    hf *wq_,*wk_,*wv_,*wo_,*w1_,*w2_;
    hf *vt,*pr,*s1,*c2p,*p2c,*p2cT;
    cudaGetSymbolAddress((void**)&hh, hb);
    cudaGetSymbolAddress((void**)&q,  qb);    cudaGetSymbolAddress((void**)&k,  kb);
    cudaGetSymbolAddress((void**)&v,  vb);    cudaGetSymbolAddress((void**)&cx, cxb);
    cudaGetSymbolAddress((void**)&ff, ffb);   cudaGetSymbolAddress((void**)&rl, rlb);
    cudaGetSymbolAddress((void**)&pk, pkb);   cudaGetSymbolAddress((void**)&pq, pqb);
    cudaGetSymbolAddress((void**)&wq_, wqt);  cudaGetSymbolAddress((void**)&wk_, wkt);
    cudaGetSymbolAddress((void**)&wv_, wvt);  cudaGetSymbolAddress((void**)&wo_, wot);
    cudaGetSymbolAddress((void**)&w1_, w1t);  cudaGetSymbolAddress((void**)&w2_, w2t);
    cudaGetSymbolAddress((void**)&vt, vtb);   cudaGetSymbolAddress((void**)&pr, prb);
    cudaGetSymbolAddress((void**)&s1, s1b);   cudaGetSymbolAddress((void**)&c2p, c2pb);
    cudaGetSymbolAddress((void**)&p2c, p2cb); cudaGetSymbolAddress((void**)&p2cT, p2cTb);

    const int SM128 = 2 * (128*128 + 128*128);   // 65536
    const int SM64  = 2 * (128*128 + 64*128);    // 49152
    cudaFuncSetAttribute(gemm_mma<128,0>, cudaFuncAttributeMaxDynamicSharedMemorySize, SM128);
    cudaFuncSetAttribute(gemm_mma<128,1>, cudaFuncAttributeMaxDynamicSharedMemorySize, SM128);
    cudaFuncSetAttribute(gemm_mma<64,0>,  cudaFuncAttributeMaxDynamicSharedMemorySize, SM64);

    embed_ln<<<BS, 256>>>(ids, segs, mask, tok, seg, elg, elb);
    cvt_fp16<<<512, 256>>>(rel, rl, (size_t)PP * DD);

    dim3 tb(32, 8);
    const ll S2 = (ll)SS * SS;
    const ll SD = (ll)SS * DD;

    for (int l = 0; l < LL; l++) {
        const float* wq = Wq + (size_t)l*DD*DD;  const float* bq_ = bq + (size_t)l*DD;
        const float* wk = Wk + (size_t)l*DD*DD;  const float* bk_ = bk + (size_t)l*DD;
        const float* wv = Wv + (size_t)l*DD*DD;  const float* bv_ = bv + (size_t)l*DD;
        const float* wo = Wo + (size_t)l*DD*DD;  const float* bo_ = bo + (size_t)l*DD;
        const float* w1 = W1 + (size_t)l*DD*FFD; const float* b1_ = b1 + (size_t)l*FFD;
        const float* w2 = W2 + (size_t)l*FFD*DD; const float* b2_ = b2 + (size_t)l*DD;
        const float* g1 = l1g + (size_t)l*DD;    const float* be1 = l1b + (size_t)l*DD;
        const float* g2 = l2g + (size_t)l*DD;    const float* be2 = l2b + (size_t)l*DD;

        transpose_cvt<<<dim3(32, 32),  tb>>>(wq, wq_, DD, DD);
        transpose_cvt<<<dim3(32, 32),  tb>>>(wk, wk_, DD, DD);
        transpose_cvt<<<dim3(32, 32),  tb>>>(wv, wv_, DD, DD);
        transpose_cvt<<<dim3(32, 32),  tb>>>(wo, wo_, DD, DD);
        transpose_cvt<<<dim3(128, 32), tb>>>(w1, w1_, DD, FFD);
        transpose_cvt<<<dim3(32, 128), tb>>>(w2, w2_, FFD, DD);

        // projections
        gemm_mma<128,0><<<dim3(8,32,1), 256, SM128>>>(hh,DD,0,0, wq_,DD,0,0,
            (float*)0, q, DD,0,0, DD, bq_);
        gemm_mma<128,0><<<dim3(8,32,1), 256, SM128>>>(hh,DD,0,0, wk_,DD,0,0,
            (float*)0, k, DD,0,0, DD, bk_);
        gemm_mma<128,0><<<dim3(8,32,1), 256, SM128>>>(hh,DD,0,0, wv_,DD,0,0,
            (float*)0, v, DD,0,0, DD, bv_);
        gemm_mma<128,0><<<dim3(8,8,1),  256, SM128>>>(rl,DD,0,0, wk_,DD,0,0,
            (float*)0, pk, DD,0,0, DD, bk_);
        gemm_mma<128,0><<<dim3(8,8,1),  256, SM128>>>(rl,DD,0,0, wq_,DD,0,0,
            (float*)0, pq, DD,0,0, DD, bq_);

        // attention scores
        gemm_mma<128,0><<<dim3(8,8,64), 256, SM128>>>(q,DD,SD,64, k,DD,SD,64,
            (float*)0, s1, SS,16*S2,S2, 64, (const float*)0);
        gemm_mma<128,0><<<dim3(8,8,64), 256, SM128>>>(q,DD,SD,64, pk,DD,0,64,
            (float*)0, c2p, PP,16*S2,S2, 64, (const float*)0);
        gemm_mma<128,0><<<dim3(8,8,64), 256, SM128>>>(k,DD,SD,64, pq,DD,0,64,
            (float*)0, p2c, PP,16*S2,S2, 64, (const float*)0);

        p2c_remap<<<dim3(32,32,64), tb>>>(p2c, p2cT);
        softmax_rel<<<dim3(SS, 64), 256>>>(s1, c2p, p2cT, mask);
        vt_cvt<<<dim3(32,2,64), tb>>>(v, vt);

        // ctx = probs @ V
        gemm_mma<64,0><<<dim3(1,8,64), 256, SM64>>>(pr,SS,16*S2,S2, vt,SS,(ll)16*64*SS,(ll)64*SS,
            (float*)0, cx, DD,SD,64, SS, (const float*)0);

        // output projection + LN
        gemm_mma<128,0><<<dim3(8,32,1), 256, SM128>>>(cx,DD,0,0, wo_,DD,0,0,
            t2, (hf*)0, DD,0,0, DD, bo_);
        add_ln<<<BS, 256>>>(h, t2, g1, be1, h);

        // FFN
        gemm_mma<128,1><<<dim3(32,32,1), 256, SM128>>>(hh,DD,0,0, w1_,DD,0,0,
            (float*)0, ff, FFD,0,0, DD, b1_);
        gemm_mma<128,0><<<dim3(8,32,1), 256, SM128>>>(ff,FFD,0,0, w2_,FFD,0,0,
            t2, (hf*)0, DD,0,0, FFD, b2_);
        add_ln<<<BS, 256>>>(h, t2, g2, be2, h);
    }

    cudaMemcpyAsync(d_out, h, (size_t)BS * DD * sizeof(float),
                    cudaMemcpyDeviceToDevice);
}